// round 1
// baseline (speedup 1.0000x reference)
#include <cuda_runtime.h>
#include <cuda_bf16.h>
#include <math.h>

// ---------------- problem constants ----------------
#define NB 4
#define NL 512
#define DM 256
#define DI 512
#define DS 16
#define DC 4
#define DTR 16
#define NLAYERS 6
#define BL (NB * NL)          // 2048 tokens
#define XR (DTR + 2 * DS)     // 48

// ---------------- device scratch (no allocations allowed) ----------------
__device__ float g_xn[BL * DM];        // rmsnorm output
__device__ float g_xz[BL * 2 * DI];    // in-proj output (x | z)
__device__ float g_u[BL * DI];         // silu(conv(x))
__device__ float g_xdbc[BL * XR];      // dt | B | C
__device__ float g_delta[BL * DI];     // softplus(dt @ dt_w + dt_b)
__device__ float g_y[BL * DI];         // gated scan output

// ---------------- helpers ----------------
__device__ __forceinline__ float siluf(float x) {
    return x / (1.0f + expf(-x));
}
__device__ __forceinline__ float softplusf(float x) {
    return x > 20.0f ? x : log1pf(expf(x));
}

// ---------------- kernels ----------------

__global__ void copy_k(const float* __restrict__ src, float* __restrict__ dst, int n) {
    int i = blockIdx.x * blockDim.x + threadIdx.x;
    if (i < n) dst[i] = src[i];
}

// one block per token, 256 threads (= DM)
__global__ void rmsnorm_k(const float* __restrict__ x, const float* __restrict__ w,
                          float* __restrict__ out) {
    int t = blockIdx.x;
    int d = threadIdx.x;
    float v = x[t * DM + d];
    float s = v * v;
    #pragma unroll
    for (int o = 16; o; o >>= 1) s += __shfl_xor_sync(0xffffffffu, s, o);
    __shared__ float sh[8];
    if ((threadIdx.x & 31) == 0) sh[threadIdx.x >> 5] = s;
    __syncthreads();
    float tot = 0.f;
    #pragma unroll
    for (int i = 0; i < 8; i++) tot += sh[i];
    float var = tot / (float)DM;
    out[t * DM + d] = v * rsqrtf(var + 1e-5f) * w[d];
}

// C[m,n] = sum_k A[m,k] * B[n,k] + bias[n] (+ resid[m,n])
// BM=BN=64, BK=16, 256 threads, 4x4 per thread
__global__ void gemm_nt(const float* __restrict__ A, const float* __restrict__ Bm,
                        const float* __restrict__ bias, const float* __restrict__ resid,
                        float* __restrict__ C, int M, int N, int K) {
    __shared__ float As[16][64];
    __shared__ float Bs[16][64];
    int bm = blockIdx.y * 64;
    int bn = blockIdx.x * 64;
    int tid = threadIdx.x;
    int tx = tid & 15;     // 0..15
    int ty = tid >> 4;     // 0..15
    float acc[4][4] = {};
    int lr = tid >> 2;           // 0..63 row within tile
    int lc = (tid & 3) * 4;      // 0,4,8,12

    for (int k0 = 0; k0 < K; k0 += 16) {
        float4 va = *(const float4*)(A + (size_t)(bm + lr) * K + k0 + lc);
        As[lc + 0][lr] = va.x; As[lc + 1][lr] = va.y;
        As[lc + 2][lr] = va.z; As[lc + 3][lr] = va.w;
        float4 vb = *(const float4*)(Bm + (size_t)(bn + lr) * K + k0 + lc);
        Bs[lc + 0][lr] = vb.x; Bs[lc + 1][lr] = vb.y;
        Bs[lc + 2][lr] = vb.z; Bs[lc + 3][lr] = vb.w;
        __syncthreads();
        #pragma unroll
        for (int k = 0; k < 16; k++) {
            float a[4], b[4];
            #pragma unroll
            for (int i = 0; i < 4; i++) a[i] = As[k][ty * 4 + i];
            #pragma unroll
            for (int j = 0; j < 4; j++) b[j] = Bs[k][tx * 4 + j];
            #pragma unroll
            for (int i = 0; i < 4; i++)
                #pragma unroll
                for (int j = 0; j < 4; j++)
                    acc[i][j] = fmaf(a[i], b[j], acc[i][j]);
        }
        __syncthreads();
    }
    #pragma unroll
    for (int i = 0; i < 4; i++) {
        int m = bm + ty * 4 + i;
        #pragma unroll
        for (int j = 0; j < 4; j++) {
            int n = bn + tx * 4 + j;
            float v = acc[i][j] + bias[n];
            if (resid) v += resid[(size_t)m * N + n];
            C[(size_t)m * N + n] = v;
        }
    }
}

// depthwise causal conv (width 4) + silu; one thread per (b,l,d)
__global__ void conv_silu_k(const float* __restrict__ xz, const float* __restrict__ cw,
                            float* __restrict__ u) {
    int idx = blockIdx.x * blockDim.x + threadIdx.x;
    if (idx >= BL * DI) return;
    int d = idx & (DI - 1);
    int t = idx >> 9;            // token index
    int l = t & (NL - 1);
    int b = t >> 9;
    float acc = 0.f;
    #pragma unroll
    for (int k = 0; k < DC; k++) {
        int ls = l - (DC - 1) + k;
        if (ls >= 0)
            acc = fmaf(cw[d * DC + k], xz[((size_t)(b * NL + ls)) * (2 * DI) + d], acc);
    }
    u[idx] = siluf(acc);
}

// xdbc[t, r] = sum_d u[t,d] * Wx[r,d]; one block per token
__global__ void xdbc_k(const float* __restrict__ u, const float* __restrict__ Wx,
                       float* __restrict__ xdbc) {
    int t = blockIdx.x;
    __shared__ float su[DI];
    for (int i = threadIdx.x; i < DI; i += blockDim.x) su[i] = u[(size_t)t * DI + i];
    __syncthreads();
    int r = threadIdx.x;
    if (r < XR) {
        float acc = 0.f;
        #pragma unroll 8
        for (int d = 0; d < DI; d++) acc = fmaf(su[d], Wx[r * DI + d], acc);
        xdbc[t * XR + r] = acc;
    }
}

// delta[t,d] = softplus(sum_r xdbc[t,r]*dtw[d,r] + dtb[d]); one thread per (t,d)
__global__ void delta_k(const float* __restrict__ xdbc, const float* __restrict__ dtw,
                        const float* __restrict__ dtb, float* __restrict__ delta) {
    int idx = blockIdx.x * blockDim.x + threadIdx.x;
    if (idx >= BL * DI) return;
    int d = idx & (DI - 1);
    int t = idx >> 9;
    float acc = dtb[d];
    #pragma unroll
    for (int r = 0; r < DTR; r++)
        acc = fmaf(xdbc[t * XR + r], dtw[d * DTR + r], acc);
    delta[idx] = softplusf(acc);
}

// selective scan + skip + gate. 16 lanes per (b,d) sequence: lane n owns state n.
// 256 threads/block = 16 groups; grid = (B*DI)/16 = 128 blocks.
__global__ void scan_k(const float* __restrict__ delta, const float* __restrict__ u,
                       const float* __restrict__ xdbc, const float* __restrict__ xz,
                       const float* __restrict__ A_log, const float* __restrict__ Dp,
                       float* __restrict__ y) {
    int gid = blockIdx.x * 16 + (threadIdx.x >> 4);   // 0..2047
    int n = threadIdx.x & 15;                          // state index
    int b = gid >> 9;                                  // /DI
    int d = gid & (DI - 1);

    float An = -expf(A_log[d * DS + n]);
    float Dd = Dp[d];
    float h = 0.f;

    int base = b * NL;
    for (int t = 0; t < NL; t++) {
        int tok = base + t;
        float dv = delta[(size_t)tok * DI + d];
        float uv = u[(size_t)tok * DI + d];
        float Bn = xdbc[tok * XR + DTR + n];
        float Cn = xdbc[tok * XR + DTR + DS + n];
        float dA = __expf(dv * An);
        h = fmaf(dA, h, dv * uv * Bn);
        float yv = h * Cn;
        yv += __shfl_xor_sync(0xffffffffu, yv, 8);
        yv += __shfl_xor_sync(0xffffffffu, yv, 4);
        yv += __shfl_xor_sync(0xffffffffu, yv, 2);
        yv += __shfl_xor_sync(0xffffffffu, yv, 1);
        if (n == 0) {
            float z = xz[(size_t)tok * (2 * DI) + DI + d];
            y[(size_t)tok * DI + d] = (yv + uv * Dd) * siluf(z);
        }
    }
}

// ---------------- launch ----------------
extern "C" void kernel_launch(void* const* d_in, const int* in_sizes, int n_in,
                              void* d_out, int out_size) {
    const float* x      = (const float*)d_in[0];
    const float* norm_w = (const float*)d_in[1];
    const float* W_in   = (const float*)d_in[2];
    const float* b_in   = (const float*)d_in[3];
    const float* conv_w = (const float*)d_in[4];
    const float* W_x    = (const float*)d_in[5];
    const float* dt_w   = (const float*)d_in[6];
    const float* dt_b   = (const float*)d_in[7];
    const float* A_log  = (const float*)d_in[8];
    const float* Dp     = (const float*)d_in[9];
    const float* W_out  = (const float*)d_in[10];
    const float* b_out  = (const float*)d_in[11];
    float* out = (float*)d_out;

    float *p_xn, *p_xz, *p_u, *p_xdbc, *p_delta, *p_y;
    cudaGetSymbolAddress((void**)&p_xn, g_xn);
    cudaGetSymbolAddress((void**)&p_xz, g_xz);
    cudaGetSymbolAddress((void**)&p_u, g_u);
    cudaGetSymbolAddress((void**)&p_xdbc, g_xdbc);
    cudaGetSymbolAddress((void**)&p_delta, g_delta);
    cudaGetSymbolAddress((void**)&p_y, g_y);

    // residual stream lives in d_out
    copy_k<<<(BL * DM + 255) / 256, 256>>>(x, out, BL * DM);

    for (int i = 0; i < NLAYERS; i++) {
        rmsnorm_k<<<BL, DM>>>(out, norm_w + i * DM, p_xn);

        // xz = xn @ W_in^T + b_in  (M=2048, N=1024, K=256)
        {
            dim3 grid((2 * DI) / 64, BL / 64);
            gemm_nt<<<grid, 256>>>(p_xn, W_in + (size_t)i * 2 * DI * DM,
                                   b_in + i * 2 * DI, nullptr, p_xz,
                                   BL, 2 * DI, DM);
        }

        conv_silu_k<<<(BL * DI + 255) / 256, 256>>>(p_xz, conv_w + i * DI * DC, p_u);

        xdbc_k<<<BL, 64>>>(p_u, W_x + (size_t)i * XR * DI, p_xdbc);

        delta_k<<<(BL * DI + 255) / 256, 256>>>(p_xdbc, dt_w + (size_t)i * DI * DTR,
                                                dt_b + i * DI, p_delta);

        scan_k<<<(NB * DI) / 16, 256>>>(p_delta, p_u, p_xdbc, p_xz,
                                        A_log + (size_t)i * DI * DS, Dp + i * DI, p_y);

        // out += y @ W_out^T + b_out  (M=2048, N=256, K=512)
        {
            dim3 grid(DM / 64, BL / 64);
            gemm_nt<<<grid, 256>>>(p_y, W_out + (size_t)i * DM * DI,
                                   b_out + i * DM, out, out,
                                   BL, DM, DI);
        }
    }
}

// round 2
// speedup vs baseline: 1.9187x; 1.9187x over previous
#include <cuda_runtime.h>
#include <cuda_bf16.h>
#include <math.h>

// ---------------- problem constants ----------------
#define NB 4
#define NL 512
#define DM 256
#define DI 512
#define DS 16
#define DC 4
#define DTR 16
#define NLAYERS 6
#define BL (NB * NL)          // 2048 tokens
#define XR (DTR + 2 * DS)     // 48

// ---------------- device scratch (no allocations allowed) ----------------
__device__ float g_xn[BL * DM];        // rmsnorm output
__device__ float g_xz[BL * 2 * DI];    // in-proj output (x | z)
__device__ float g_u[BL * DI];         // silu(conv(x))
__device__ float g_xdbc[BL * XR];      // dt | B | C
__device__ float g_delta[BL * DI];     // softplus(dt @ dt_w + dt_b)
__device__ float g_y[BL * DI];         // gated scan output

// ---------------- helpers ----------------
__device__ __forceinline__ float siluf(float x) {
    return x / (1.0f + __expf(-x));
}
__device__ __forceinline__ float softplusf(float x) {
    return x > 20.0f ? x : log1pf(__expf(x));
}

// ---------------- kernels ----------------

__global__ void copy_k(const float* __restrict__ src, float* __restrict__ dst, int n) {
    int i = blockIdx.x * blockDim.x + threadIdx.x;
    if (i < n) dst[i] = src[i];
}

// one block per token, 256 threads (= DM)
__global__ void rmsnorm_k(const float* __restrict__ x, const float* __restrict__ w,
                          float* __restrict__ out) {
    int t = blockIdx.x;
    int d = threadIdx.x;
    float v = x[t * DM + d];
    float s = v * v;
    #pragma unroll
    for (int o = 16; o; o >>= 1) s += __shfl_xor_sync(0xffffffffu, s, o);
    __shared__ float sh[8];
    if ((threadIdx.x & 31) == 0) sh[threadIdx.x >> 5] = s;
    __syncthreads();
    float tot = 0.f;
    #pragma unroll
    for (int i = 0; i < 8; i++) tot += sh[i];
    float var = tot / (float)DM;
    out[t * DM + d] = v * rsqrtf(var + 1e-5f) * w[d];
}

// C[m,n] = sum_k A[m,k] * B[n,k] + bias[n] (+ resid[m,n])
// Templated tile: BM x BN, BK=16, 256 threads, TM x TN per thread.
// Double-buffered shared memory; global loads for tile k+1 overlap compute of k.
template<int BM, int BN, int TM, int TN>
__global__ void __launch_bounds__(256)
gemm_nt(const float* __restrict__ A, const float* __restrict__ Bm,
        const float* __restrict__ bias, const float* __restrict__ resid,
        float* __restrict__ C, int M, int N, int K) {
    constexpr int BK = 16;
    constexpr int LA = (BM * BK) / (256 * 4);   // float4 A loads per thread
    constexpr int LB = (BN * BK) / (256 * 4);   // float4 B loads per thread
    static_assert(LA >= 1 && LB >= 1, "tile too small");

    __shared__ float As[2][BK][BM];
    __shared__ float Bs[2][BK][BN];

    const int bm = blockIdx.y * BM;
    const int bn = blockIdx.x * BN;
    const int tid = threadIdx.x;
    const int tx = tid % (BN / TN);
    const int ty = tid / (BN / TN);

    float acc[TM][TN];
    #pragma unroll
    for (int i = 0; i < TM; i++)
        #pragma unroll
        for (int j = 0; j < TN; j++) acc[i][j] = 0.f;

    // load helpers: linear float4 index over the tile
    auto load_tileA = [&](int k0, float4* r) {
        #pragma unroll
        for (int i = 0; i < LA; i++) {
            int lin = tid + 256 * i;            // float4 index
            int row = lin >> 2;                  // BK/4 = 4 float4 per row
            int col4 = lin & 3;
            r[i] = *(const float4*)(A + (size_t)(bm + row) * K + k0 + col4 * 4);
        }
    };
    auto load_tileB = [&](int k0, float4* r) {
        #pragma unroll
        for (int i = 0; i < LB; i++) {
            int lin = tid + 256 * i;
            int row = lin >> 2;
            int col4 = lin & 3;
            r[i] = *(const float4*)(Bm + (size_t)(bn + row) * K + k0 + col4 * 4);
        }
    };
    auto store_tileA = [&](int buf, const float4* r) {
        #pragma unroll
        for (int i = 0; i < LA; i++) {
            int lin = tid + 256 * i;
            int row = lin >> 2;
            int c = (lin & 3) * 4;
            As[buf][c + 0][row] = r[i].x;
            As[buf][c + 1][row] = r[i].y;
            As[buf][c + 2][row] = r[i].z;
            As[buf][c + 3][row] = r[i].w;
        }
    };
    auto store_tileB = [&](int buf, const float4* r) {
        #pragma unroll
        for (int i = 0; i < LB; i++) {
            int lin = tid + 256 * i;
            int row = lin >> 2;
            int c = (lin & 3) * 4;
            Bs[buf][c + 0][row] = r[i].x;
            Bs[buf][c + 1][row] = r[i].y;
            Bs[buf][c + 2][row] = r[i].z;
            Bs[buf][c + 3][row] = r[i].w;
        }
    };

    // prologue
    {
        float4 ra[LA], rb[LB];
        load_tileA(0, ra); load_tileB(0, rb);
        store_tileA(0, ra); store_tileB(0, rb);
    }
    __syncthreads();

    int buf = 0;
    for (int k0 = 0; k0 < K; k0 += BK) {
        float4 ra[LA], rb[LB];
        const bool has_next = (k0 + BK) < K;
        if (has_next) { load_tileA(k0 + BK, ra); load_tileB(k0 + BK, rb); }

        #pragma unroll
        for (int k = 0; k < BK; k++) {
            float a[TM], b[TN];
            #pragma unroll
            for (int i = 0; i < TM; i++) a[i] = As[buf][k][ty * TM + i];
            #pragma unroll
            for (int j = 0; j < TN; j++) b[j] = Bs[buf][k][tx * TN + j];
            #pragma unroll
            for (int i = 0; i < TM; i++)
                #pragma unroll
                for (int j = 0; j < TN; j++)
                    acc[i][j] = fmaf(a[i], b[j], acc[i][j]);
        }

        if (has_next) {
            store_tileA(buf ^ 1, ra); store_tileB(buf ^ 1, rb);
            __syncthreads();
            buf ^= 1;
        }
    }

    #pragma unroll
    for (int i = 0; i < TM; i++) {
        int m = bm + ty * TM + i;
        #pragma unroll
        for (int j = 0; j < TN; j++) {
            int n = bn + tx * TN + j;
            float v = acc[i][j] + bias[n];
            if (resid) v += resid[(size_t)m * N + n];
            C[(size_t)m * N + n] = v;
        }
    }
}

// depthwise causal conv (width 4) + silu; one thread per (b,l,d)
__global__ void conv_silu_k(const float* __restrict__ xz, const float* __restrict__ cw,
                            float* __restrict__ u) {
    int idx = blockIdx.x * blockDim.x + threadIdx.x;
    if (idx >= BL * DI) return;
    int d = idx & (DI - 1);
    int t = idx >> 9;            // token index
    int l = t & (NL - 1);
    int b = t >> 9;
    float acc = 0.f;
    #pragma unroll
    for (int k = 0; k < DC; k++) {
        int ls = l - (DC - 1) + k;
        if (ls >= 0)
            acc = fmaf(cw[d * DC + k], xz[((size_t)(b * NL + ls)) * (2 * DI) + d], acc);
    }
    u[idx] = siluf(acc);
}

// xdbc[t, r] = sum_d u[t,d] * Wx[r,d]
// one block per token, 8 warps; each warp does 6 of the 48 r-rows,
// lanes sweep d with float4 (fully coalesced Wx reads, smem-staged u).
__global__ void xdbc_k(const float* __restrict__ u, const float* __restrict__ Wx,
                       float* __restrict__ xdbc) {
    int t = blockIdx.x;
    __shared__ float su[DI];
    #pragma unroll
    for (int i = threadIdx.x; i < DI; i += 256) su[i] = u[(size_t)t * DI + i];
    __syncthreads();
    int w = threadIdx.x >> 5;
    int lane = threadIdx.x & 31;
    const float4* su4 = (const float4*)su;
    for (int r = w; r < XR; r += 8) {
        const float4* Wr = (const float4*)(Wx + (size_t)r * DI);
        float acc = 0.f;
        #pragma unroll
        for (int i = 0; i < 4; i++) {
            float4 wv = Wr[lane + 32 * i];
            float4 uv = su4[lane + 32 * i];
            acc = fmaf(wv.x, uv.x, acc);
            acc = fmaf(wv.y, uv.y, acc);
            acc = fmaf(wv.z, uv.z, acc);
            acc = fmaf(wv.w, uv.w, acc);
        }
        #pragma unroll
        for (int o = 16; o; o >>= 1) acc += __shfl_xor_sync(0xffffffffu, acc, o);
        if (lane == 0) xdbc[t * XR + r] = acc;
    }
}

// delta[t,d] = softplus(sum_r xdbc[t,r]*dtw[d,r] + dtb[d])
// dtw staged in smem with stride-17 padding (conflict-free).
__global__ void delta_k(const float* __restrict__ xdbc, const float* __restrict__ dtw,
                        const float* __restrict__ dtb, float* __restrict__ delta) {
    __shared__ float sdt[256 * 17];
    int blk = blockIdx.x;
    int tid = threadIdx.x;
    int d0 = (blk * 256) & (DI - 1);       // 0 or 256
    for (int i = tid; i < 256 * DTR; i += 256) {
        int d = i >> 4, r = i & 15;
        sdt[d * 17 + r] = dtw[(size_t)(d0 + d) * DTR + r];
    }
    __syncthreads();
    int idx = blk * 256 + tid;
    int d = idx & (DI - 1);
    int t = idx >> 9;
    float acc = dtb[d];
    const float* xr = xdbc + t * XR;
    #pragma unroll
    for (int r = 0; r < DTR; r++)
        acc = fmaf(xr[r], sdt[tid * 17 + r], acc);
    delta[idx] = softplusf(acc);
}

// selective scan + skip + gate. 16 lanes per (b,d) sequence: lane n owns state n.
// Software-pipelined: t+1 loads issue before t's compute (off the h-chain).
__global__ void scan_k(const float* __restrict__ delta, const float* __restrict__ u,
                       const float* __restrict__ xdbc, const float* __restrict__ xz,
                       const float* __restrict__ A_log, const float* __restrict__ Dp,
                       float* __restrict__ y) {
    int gid = blockIdx.x * 16 + (threadIdx.x >> 4);   // 0..2047
    int n = threadIdx.x & 15;                          // state index
    int b = gid >> 9;                                  // /DI
    int d = gid & (DI - 1);

    float An = -__expf(A_log[d * DS + n]);
    float Dd = Dp[d];
    float h = 0.f;

    int base = b * NL;
    // prefetch t=0
    float dv = delta[(size_t)base * DI + d];
    float uv = u[(size_t)base * DI + d];
    float Bn = xdbc[base * XR + DTR + n];
    float Cn = xdbc[base * XR + DTR + DS + n];

    for (int t = 0; t < NL; t++) {
        float dv_c = dv, uv_c = uv, Bn_c = Bn, Cn_c = Cn;
        int tok = base + t;
        if (t + 1 < NL) {
            int tk = tok + 1;
            dv = delta[(size_t)tk * DI + d];
            uv = u[(size_t)tk * DI + d];
            Bn = xdbc[tk * XR + DTR + n];
            Cn = xdbc[tk * XR + DTR + DS + n];
        }
        float dA = __expf(dv_c * An);
        h = fmaf(dA, h, dv_c * uv_c * Bn_c);
        float yv = h * Cn_c;
        yv += __shfl_xor_sync(0xffffffffu, yv, 8);
        yv += __shfl_xor_sync(0xffffffffu, yv, 4);
        yv += __shfl_xor_sync(0xffffffffu, yv, 2);
        yv += __shfl_xor_sync(0xffffffffu, yv, 1);
        if (n == 0) {
            float z = xz[(size_t)tok * (2 * DI) + DI + d];
            y[(size_t)tok * DI + d] = (yv + uv_c * Dd) * siluf(z);
        }
    }
}

// ---------------- launch ----------------
extern "C" void kernel_launch(void* const* d_in, const int* in_sizes, int n_in,
                              void* d_out, int out_size) {
    const float* x      = (const float*)d_in[0];
    const float* norm_w = (const float*)d_in[1];
    const float* W_in   = (const float*)d_in[2];
    const float* b_in   = (const float*)d_in[3];
    const float* conv_w = (const float*)d_in[4];
    const float* W_x    = (const float*)d_in[5];
    const float* dt_w   = (const float*)d_in[6];
    const float* dt_b   = (const float*)d_in[7];
    const float* A_log  = (const float*)d_in[8];
    const float* Dp     = (const float*)d_in[9];
    const float* W_out  = (const float*)d_in[10];
    const float* b_out  = (const float*)d_in[11];
    float* out = (float*)d_out;

    float *p_xn, *p_xz, *p_u, *p_xdbc, *p_delta, *p_y;
    cudaGetSymbolAddress((void**)&p_xn, g_xn);
    cudaGetSymbolAddress((void**)&p_xz, g_xz);
    cudaGetSymbolAddress((void**)&p_u, g_u);
    cudaGetSymbolAddress((void**)&p_xdbc, g_xdbc);
    cudaGetSymbolAddress((void**)&p_delta, g_delta);
    cudaGetSymbolAddress((void**)&p_y, g_y);

    // residual stream lives in d_out
    copy_k<<<(BL * DM + 255) / 256, 256>>>(x, out, BL * DM);

    for (int i = 0; i < NLAYERS; i++) {
        rmsnorm_k<<<BL, DM>>>(out, norm_w + i * DM, p_xn);

        // xz = xn @ W_in^T + b_in  (M=2048, N=1024, K=256) — 128x64 tile
        {
            dim3 grid((2 * DI) / 64, BL / 128);
            gemm_nt<128, 64, 8, 4><<<grid, 256>>>(p_xn, W_in + (size_t)i * 2 * DI * DM,
                                                  b_in + i * 2 * DI, nullptr, p_xz,
                                                  BL, 2 * DI, DM);
        }

        conv_silu_k<<<(BL * DI + 255) / 256, 256>>>(p_xz, conv_w + i * DI * DC, p_u);

        xdbc_k<<<BL, 256>>>(p_u, W_x + (size_t)i * XR * DI, p_xdbc);

        delta_k<<<(BL * DI) / 256, 256>>>(p_xdbc, dt_w + (size_t)i * DI * DTR,
                                          dt_b + i * DI, p_delta);

        scan_k<<<(NB * DI) / 16, 256>>>(p_delta, p_u, p_xdbc, p_xz,
                                        A_log + (size_t)i * DI * DS, Dp + i * DI, p_y);

        // out += y @ W_out^T + b_out  (M=2048, N=256, K=512) — 64x64 tile, 128 blocks
        {
            dim3 grid(DM / 64, BL / 64);
            gemm_nt<64, 64, 4, 4><<<grid, 256>>>(p_y, W_out + (size_t)i * DM * DI,
                                                 b_out + i * DM, out, out,
                                                 BL, DM, DI);
        }
    }
}

// round 3
// speedup vs baseline: 3.6695x; 1.9125x over previous
#include <cuda_runtime.h>
#include <cuda_bf16.h>
#include <math.h>
#include <stdint.h>

// ---------------- problem constants ----------------
#define NB 4
#define NL 512
#define DM 256
#define DI 512
#define DS 16
#define DC 4
#define DTR 16
#define NLAYERS 6
#define BL (NB * NL)          // 2048 tokens
#define XR (DTR + 2 * DS)     // 48

// ---------------- device scratch ----------------
__device__ float g_xn[BL * DM];
__device__ float g_xz[BL * 2 * DI];
__device__ float g_u[BL * DI];
__device__ float g_xdbc[BL * XR];
__device__ float g_delta[BL * DI];
__device__ float g_y[BL * DI];

// ---------------- helpers ----------------
__device__ __forceinline__ float siluf(float x) {
    return x / (1.0f + __expf(-x));
}
__device__ __forceinline__ float softplusf(float x) {
    return x > 20.0f ? x : log1pf(__expf(x));
}
__device__ __forceinline__ uint32_t f2tf32(float f) {
    uint32_t u;
    asm("cvt.rna.tf32.f32 %0, %1;" : "=r"(u) : "f"(f));
    return u;
}
__device__ __forceinline__ void mma_tf32(float* c, const uint32_t* a, const uint32_t* b) {
    asm("mma.sync.aligned.m16n8k8.row.col.f32.tf32.tf32.f32 "
        "{%0,%1,%2,%3},{%4,%5,%6,%7},{%8,%9},{%0,%1,%2,%3};"
        : "+f"(c[0]), "+f"(c[1]), "+f"(c[2]), "+f"(c[3])
        : "r"(a[0]), "r"(a[1]), "r"(a[2]), "r"(a[3]), "r"(b[0]), "r"(b[1]));
}

// ---------------- kernels ----------------

__global__ void copy_k(const float* __restrict__ src, float* __restrict__ dst, int n) {
    int i = blockIdx.x * blockDim.x + threadIdx.x;
    if (i < n) dst[i] = src[i];
}

__global__ void rmsnorm_k(const float* __restrict__ x, const float* __restrict__ w,
                          float* __restrict__ out) {
    int t = blockIdx.x;
    int d = threadIdx.x;
    float v = x[t * DM + d];
    float s = v * v;
    #pragma unroll
    for (int o = 16; o; o >>= 1) s += __shfl_xor_sync(0xffffffffu, s, o);
    __shared__ float sh[8];
    if ((threadIdx.x & 31) == 0) sh[threadIdx.x >> 5] = s;
    __syncthreads();
    float tot = 0.f;
    #pragma unroll
    for (int i = 0; i < 8; i++) tot += sh[i];
    float var = tot / (float)DM;
    out[t * DM + d] = v * rsqrtf(var + 1e-5f) * w[d];
}

// -------- tf32 tensor-core GEMM: C[m,n] = sum_k A[m,k]*B[n,k] + bias[n] (+resid) --------
// 256 threads = 8 warps arranged WM x WN; warp tile (BM/WM) x (BN/WN); BK=32.
// Register-prefetch of next K tile overlaps mma compute; smem stores tf32 bits.
template<int BM, int BN, int WM, int WN>
__global__ void __launch_bounds__(256)
gemm_tf32(const float* __restrict__ A, const float* __restrict__ Bm,
          const float* __restrict__ bias, const float* __restrict__ resid,
          float* __restrict__ C, int M, int N, int K) {
    constexpr int BK  = 32;
    constexpr int AST = BK + 4;            // padded stride (conflict-free frag loads)
    constexpr int WTM = BM / WM;
    constexpr int WTN = BN / WN;
    constexpr int AM  = WTM / 16;          // m16 atoms per warp
    constexpr int AN  = WTN / 8;           // n8 atoms per warp
    constexpr int LA  = BM * BK / (256 * 4);
    constexpr int LB  = BN * BK / (256 * 4);

    __shared__ uint32_t As[BM * AST];
    __shared__ uint32_t Bs[BN * AST];

    const int bm = blockIdx.y * BM;
    const int bn = blockIdx.x * BN;
    const int tid = threadIdx.x;
    const int wid = tid >> 5;
    const int lane = tid & 31;
    const int wm = wid / WN;
    const int wn = wid % WN;
    const int group = lane >> 2;
    const int q = lane & 3;

    float acc[AM][AN][4];
    #pragma unroll
    for (int i = 0; i < AM; i++)
        #pragma unroll
        for (int j = 0; j < AN; j++)
            #pragma unroll
            for (int r = 0; r < 4; r++) acc[i][j][r] = 0.f;

    float4 ra[LA], rb[LB];
    auto load_g = [&](int k0) {
        #pragma unroll
        for (int i = 0; i < LA; i++) {
            int lin = tid + 256 * i;
            int row = lin >> 3;
            int c = (lin & 7) * 4;
            ra[i] = *(const float4*)(A + (size_t)(bm + row) * K + k0 + c);
        }
        #pragma unroll
        for (int i = 0; i < LB; i++) {
            int lin = tid + 256 * i;
            int row = lin >> 3;
            int c = (lin & 7) * 4;
            rb[i] = *(const float4*)(Bm + (size_t)(bn + row) * K + k0 + c);
        }
    };
    auto store_s = [&]() {
        #pragma unroll
        for (int i = 0; i < LA; i++) {
            int lin = tid + 256 * i;
            int row = lin >> 3;
            int c = (lin & 7) * 4;
            uint32_t* p = &As[row * AST + c];
            p[0] = f2tf32(ra[i].x); p[1] = f2tf32(ra[i].y);
            p[2] = f2tf32(ra[i].z); p[3] = f2tf32(ra[i].w);
        }
        #pragma unroll
        for (int i = 0; i < LB; i++) {
            int lin = tid + 256 * i;
            int row = lin >> 3;
            int c = (lin & 7) * 4;
            uint32_t* p = &Bs[row * AST + c];
            p[0] = f2tf32(rb[i].x); p[1] = f2tf32(rb[i].y);
            p[2] = f2tf32(rb[i].z); p[3] = f2tf32(rb[i].w);
        }
    };

    load_g(0);
    store_s();
    __syncthreads();

    for (int k0 = 0; k0 < K; k0 += BK) {
        const bool has_next = (k0 + BK) < K;
        if (has_next) load_g(k0 + BK);   // global loads overlap the mma work below

        #pragma unroll
        for (int ks = 0; ks < 4; ks++) {
            const int kb = ks * 8;
            uint32_t af[AM][4], bf[AN][2];
            #pragma unroll
            for (int i = 0; i < AM; i++) {
                int r0 = wm * WTM + i * 16 + group;
                af[i][0] = As[r0 * AST + kb + q];
                af[i][1] = As[(r0 + 8) * AST + kb + q];
                af[i][2] = As[r0 * AST + kb + q + 4];
                af[i][3] = As[(r0 + 8) * AST + kb + q + 4];
            }
            #pragma unroll
            for (int j = 0; j < AN; j++) {
                int n0 = wn * WTN + j * 8 + group;
                bf[j][0] = Bs[n0 * AST + kb + q];
                bf[j][1] = Bs[n0 * AST + kb + q + 4];
            }
            #pragma unroll
            for (int i = 0; i < AM; i++)
                #pragma unroll
                for (int j = 0; j < AN; j++)
                    mma_tf32(acc[i][j], af[i], bf[j]);
        }

        if (has_next) {
            __syncthreads();
            store_s();
            __syncthreads();
        }
    }

    // epilogue: c0,c1 -> (row, 2q), (row, 2q+1); c2,c3 -> (row+8, ...)
    #pragma unroll
    for (int i = 0; i < AM; i++) {
        int r0 = bm + wm * WTM + i * 16 + group;
        #pragma unroll
        for (int j = 0; j < AN; j++) {
            int c0 = bn + wn * WTN + j * 8 + q * 2;
            float bi0 = bias[c0], bi1 = bias[c0 + 1];
            float v00 = acc[i][j][0] + bi0, v01 = acc[i][j][1] + bi1;
            float v10 = acc[i][j][2] + bi0, v11 = acc[i][j][3] + bi1;
            float* p0 = C + (size_t)r0 * N + c0;
            float* p1 = C + (size_t)(r0 + 8) * N + c0;
            if (resid) {
                const float* q0 = resid + (size_t)r0 * N + c0;
                const float* q1 = resid + (size_t)(r0 + 8) * N + c0;
                v00 += q0[0]; v01 += q0[1]; v10 += q1[0]; v11 += q1[1];
            }
            *(float2*)p0 = make_float2(v00, v01);
            *(float2*)p1 = make_float2(v10, v11);
        }
    }
}

// -------- fused conv+silu -> x-proj -> delta, one block per token --------
__global__ void __launch_bounds__(256)
fused_mid_k(const float* __restrict__ xz, const float* __restrict__ cw,
            const float* __restrict__ Wx, const float* __restrict__ dtw,
            const float* __restrict__ dtb,
            float* __restrict__ u, float* __restrict__ xdbc,
            float* __restrict__ delta) {
    int t = blockIdx.x;
    int b = t >> 9;
    int l = t & (NL - 1);
    int tid = threadIdx.x;

    __shared__ float su[DI];
    __shared__ float sxd[XR];

    // conv + silu (2 channels per thread)
    #pragma unroll
    for (int i = 0; i < 2; i++) {
        int d = tid + i * 256;
        float acc = 0.f;
        #pragma unroll
        for (int k = 0; k < DC; k++) {
            int ls = l - (DC - 1) + k;
            if (ls >= 0)
                acc = fmaf(cw[d * DC + k], xz[(size_t)(b * NL + ls) * (2 * DI) + d], acc);
        }
        float uu = siluf(acc);
        su[d] = uu;
        u[(size_t)t * DI + d] = uu;
    }
    __syncthreads();

    // x-proj: 48 dot products of length 512, warp per r
    int w = tid >> 5, lane = tid & 31;
    const float4* su4 = (const float4*)su;
    for (int r = w; r < XR; r += 8) {
        const float4* Wr = (const float4*)(Wx + (size_t)r * DI);
        float acc = 0.f;
        #pragma unroll
        for (int i = 0; i < 4; i++) {
            float4 wv = Wr[lane + 32 * i];
            float4 uv = su4[lane + 32 * i];
            acc = fmaf(wv.x, uv.x, acc);
            acc = fmaf(wv.y, uv.y, acc);
            acc = fmaf(wv.z, uv.z, acc);
            acc = fmaf(wv.w, uv.w, acc);
        }
        #pragma unroll
        for (int o = 16; o; o >>= 1) acc += __shfl_xor_sync(0xffffffffu, acc, o);
        if (lane == 0) { sxd[r] = acc; xdbc[t * XR + r] = acc; }
    }
    __syncthreads();

    // delta (2 channels per thread); dt part of sxd broadcast from smem
    #pragma unroll
    for (int i = 0; i < 2; i++) {
        int d = tid + i * 256;
        float acc = dtb[d];
        const float4* dw4 = (const float4*)(dtw + (size_t)d * DTR);
        #pragma unroll
        for (int rr = 0; rr < 4; rr++) {
            float4 wv = dw4[rr];
            acc = fmaf(sxd[rr * 4 + 0], wv.x, acc);
            acc = fmaf(sxd[rr * 4 + 1], wv.y, acc);
            acc = fmaf(sxd[rr * 4 + 2], wv.z, acc);
            acc = fmaf(sxd[rr * 4 + 3], wv.w, acc);
        }
        delta[(size_t)t * DI + d] = softplusf(acc);
    }
}

// -------- selective scan, 16 lanes per (b,d), 4-step prefetch pipeline --------
__global__ void __launch_bounds__(256)
scan_k(const float* __restrict__ delta, const float* __restrict__ u,
       const float* __restrict__ xdbc, const float* __restrict__ xz,
       const float* __restrict__ A_log, const float* __restrict__ Dp,
       float* __restrict__ y) {
    int gid = blockIdx.x * 16 + (threadIdx.x >> 4);
    int n = threadIdx.x & 15;
    int b = gid >> 9;
    int d = gid & (DI - 1);

    float An = -__expf(A_log[d * DS + n]);
    float Dd = Dp[d];
    bool w0 = (n == 0);
    float h = 0.f;

    int base = b * NL;
    const float* dp = delta + (size_t)base * DI + d;
    const float* up = u + (size_t)base * DI + d;
    const float* Bp = xdbc + base * XR + DTR + n;
    const float* Cp = Bp + DS;
    const float* zp = xz + (size_t)base * (2 * DI) + DI + d;

    float cd[4], cu[4], cB[4], cC[4], cz[4];
    #pragma unroll
    for (int i = 0; i < 4; i++) {
        cd[i] = dp[i * DI];
        cu[i] = up[i * DI];
        cB[i] = Bp[i * XR];
        cC[i] = Cp[i * XR];
        cz[i] = w0 ? zp[(size_t)i * (2 * DI)] : 0.f;
    }

    for (int t0 = 0; t0 < NL; t0 += 4) {
        float nd[4], nu[4], nB[4], nC[4], nz[4];
        if (t0 + 4 < NL) {
            #pragma unroll
            for (int i = 0; i < 4; i++) {
                int tt = t0 + 4 + i;
                nd[i] = dp[tt * DI];
                nu[i] = up[tt * DI];
                nB[i] = Bp[tt * XR];
                nC[i] = Cp[tt * XR];
                nz[i] = w0 ? zp[(size_t)tt * (2 * DI)] : 0.f;
            }
        }
        #pragma unroll
        for (int i = 0; i < 4; i++) {
            float dA = __expf(cd[i] * An);
            h = fmaf(dA, h, cd[i] * cu[i] * cB[i]);
            float yv = h * cC[i];
            yv += __shfl_xor_sync(0xffffffffu, yv, 8);
            yv += __shfl_xor_sync(0xffffffffu, yv, 4);
            yv += __shfl_xor_sync(0xffffffffu, yv, 2);
            yv += __shfl_xor_sync(0xffffffffu, yv, 1);
            if (w0)
                y[(size_t)(base + t0 + i) * DI + d] = (yv + cu[i] * Dd) * siluf(cz[i]);
        }
        #pragma unroll
        for (int i = 0; i < 4; i++) {
            cd[i] = nd[i]; cu[i] = nu[i]; cB[i] = nB[i]; cC[i] = nC[i]; cz[i] = nz[i];
        }
    }
}

// ---------------- launch ----------------
extern "C" void kernel_launch(void* const* d_in, const int* in_sizes, int n_in,
                              void* d_out, int out_size) {
    const float* x      = (const float*)d_in[0];
    const float* norm_w = (const float*)d_in[1];
    const float* W_in   = (const float*)d_in[2];
    const float* b_in   = (const float*)d_in[3];
    const float* conv_w = (const float*)d_in[4];
    const float* W_x    = (const float*)d_in[5];
    const float* dt_w   = (const float*)d_in[6];
    const float* dt_b   = (const float*)d_in[7];
    const float* A_log  = (const float*)d_in[8];
    const float* Dp     = (const float*)d_in[9];
    const float* W_out  = (const float*)d_in[10];
    const float* b_out  = (const float*)d_in[11];
    float* out = (float*)d_out;

    float *p_xn, *p_xz, *p_u, *p_xdbc, *p_delta, *p_y;
    cudaGetSymbolAddress((void**)&p_xn, g_xn);
    cudaGetSymbolAddress((void**)&p_xz, g_xz);
    cudaGetSymbolAddress((void**)&p_u, g_u);
    cudaGetSymbolAddress((void**)&p_xdbc, g_xdbc);
    cudaGetSymbolAddress((void**)&p_delta, g_delta);
    cudaGetSymbolAddress((void**)&p_y, g_y);

    copy_k<<<(BL * DM + 255) / 256, 256>>>(x, out, BL * DM);

    for (int i = 0; i < NLAYERS; i++) {
        rmsnorm_k<<<BL, DM>>>(out, norm_w + i * DM, p_xn);

        // xz = xn @ W_in^T + b_in  (M=2048, N=1024, K=256)
        {
            dim3 grid((2 * DI) / 64, BL / 128);
            gemm_tf32<128, 64, 4, 2><<<grid, 256>>>(
                p_xn, W_in + (size_t)i * 2 * DI * DM,
                b_in + i * 2 * DI, nullptr, p_xz, BL, 2 * DI, DM);
        }

        fused_mid_k<<<BL, 256>>>(p_xz, conv_w + i * DI * DC,
                                 W_x + (size_t)i * XR * DI,
                                 dt_w + (size_t)i * DI * DTR, dt_b + i * DI,
                                 p_u, p_xdbc, p_delta);

        scan_k<<<(NB * DI) / 16, 256>>>(p_delta, p_u, p_xdbc, p_xz,
                                        A_log + (size_t)i * DI * DS, Dp + i * DI, p_y);

        // out += y @ W_out^T + b_out  (M=2048, N=256, K=512)
        {
            dim3 grid(DM / 64, BL / 64);
            gemm_tf32<64, 64, 2, 4><<<grid, 256>>>(
                p_y, W_out + (size_t)i * DM * DI,
                b_out + i * DM, out, out, BL, DM, DI);
        }
    }
}